// round 1
// baseline (speedup 1.0000x reference)
#include <cuda_runtime.h>
#include <cuda_bf16.h>

#define N_SYSTEMS 16
#define D 64
#define EPS 1e-12f

// Global scratch (no dynamic allocation allowed).
__device__ float g_sums[N_SYSTEMS * D];
__device__ float g_counts[N_SYSTEMS];

__global__ void zero_scratch_kernel() {
    int t = threadIdx.x;
    if (t < N_SYSTEMS * D) g_sums[t] = 0.0f;
    if (t < N_SYSTEMS) g_counts[t] = 0.0f;
}

// One warp per row: normalize + accumulate into per-block shared sums,
// then flush block sums to global with atomics.
__global__ void __launch_bounds__(256) accumulate_kernel(
    const float* __restrict__ out, const int* __restrict__ system, int n_rows)
{
    __shared__ float ssum[N_SYSTEMS * D];   // 4 KB
    __shared__ float scount[N_SYSTEMS];

    int tid = threadIdx.x;
    int lane = tid & 31;
    int warp = tid >> 5;

    // Zero shared accumulators.
    for (int i = tid; i < N_SYSTEMS * D; i += blockDim.x) ssum[i] = 0.0f;
    if (tid < N_SYSTEMS) scount[tid] = 0.0f;
    __syncthreads();

    int warps_per_block = blockDim.x >> 5;
    int global_warp = blockIdx.x * warps_per_block + warp;
    int total_warps = gridDim.x * warps_per_block;

    for (int r = global_warp; r < n_rows; r += total_warps) {
        const float* row = out + (size_t)r * D;
        float v0 = row[lane];        // dims [0,32): coalesced 128B
        float v1 = row[lane + 32];   // dims [32,64): coalesced 128B

        // Warp-reduce sum of squares.
        float ss = v0 * v0 + v1 * v1;
        #pragma unroll
        for (int off = 16; off > 0; off >>= 1)
            ss += __shfl_xor_sync(0xFFFFFFFFu, ss, off);

        float norm = sqrtf(ss);
        norm = fmaxf(norm, EPS);
        float inv = 1.0f / norm;

        int sys = system[r];  // same for all lanes (broadcast L1 hit)
        // Shared atomics: bank index = lane (distinct per lane) for both adds.
        atomicAdd(&ssum[sys * D + lane], v0 * inv);
        atomicAdd(&ssum[sys * D + lane + 32], v1 * inv);
        if (lane == 0) atomicAdd(&scount[sys], 1.0f);
    }

    __syncthreads();
    // Flush block-level partials to global.
    for (int i = tid; i < N_SYSTEMS * D; i += blockDim.x) {
        float v = ssum[i];
        if (v != 0.0f) atomicAdd(&g_sums[i], v);
    }
    if (tid < N_SYSTEMS) {
        float c = scount[tid];
        if (c != 0.0f) atomicAdd(&g_counts[tid], c);
    }
}

// Single-block epilogue: means -> Gram -> distance matrix.
__global__ void __launch_bounds__(256) finalize_kernel(float* __restrict__ dist)
{
    __shared__ float means[N_SYSTEMS * D];
    int t = threadIdx.x;

    // Load sums, divide by counts.
    for (int i = t; i < N_SYSTEMS * D; i += 256) {
        int s = i / D;
        float c = g_counts[s];
        means[i] = g_sums[i] / c;
    }
    __syncthreads();

    // 256 threads -> 256 (i,j) pairs.
    int i = t >> 4;
    int j = t & 15;
    float dot = 0.0f;
    #pragma unroll
    for (int d = 0; d < D; d++)
        dot += means[i * D + d] * means[j * D + d];

    float v = 0.5f - 0.5f * dot;
    if (i == j) v = 0.0f;
    dist[i * N_SYSTEMS + j] = v;
}

extern "C" void kernel_launch(void* const* d_in, const int* in_sizes, int n_in,
                              void* d_out, int out_size) {
    const float* out_mat = (const float*)d_in[0];
    const int* system = (const int*)d_in[1];
    float* dist = (float*)d_out;
    int n_rows = in_sizes[1];  // system has one entry per row

    zero_scratch_kernel<<<1, 1024>>>();
    accumulate_kernel<<<1184, 256>>>(out_mat, system, n_rows);
    finalize_kernel<<<1, 256>>>(dist);
}

// round 2
// speedup vs baseline: 2.4481x; 2.4481x over previous
#include <cuda_runtime.h>
#include <cuda_bf16.h>

#define N_SYSTEMS 16
#define D 64
#define NWARPS 8           // warps per block
#define NBLOCKS 888        // 148 SMs * 6 blocks (33.3 KB smem each)

// Global scratch (no dynamic allocation allowed).
__device__ float g_sums[N_SYSTEMS * D];
__device__ float g_counts[N_SYSTEMS];

__global__ void zero_scratch_kernel() {
    int t = threadIdx.x;
    if (t < N_SYSTEMS * D) g_sums[t] = 0.0f;
    if (t < N_SYSTEMS) g_counts[t] = 0.0f;
}

// Warp processes a PAIR of rows per iteration:
//   lanes 0-15  -> row 2p   (float4 chunk lane)
//   lanes 16-31 -> row 2p+1 (float4 chunk lane-16)
// One LDG.128 warp-instruction = 512B = both rows, fully coalesced.
// Accumulation into per-warp private shared buffers (no atomics).
__global__ void __launch_bounds__(256) accumulate_kernel(
    const float* __restrict__ out, const int* __restrict__ system, int n_rows)
{
    __shared__ float4 ssum4[NWARPS][N_SYSTEMS][16];  // 32 KB
    __shared__ float  scount[NWARPS][N_SYSTEMS];     // 512 B

    const int tid  = threadIdx.x;
    const int lane = tid & 31;
    const int warp = tid >> 5;
    const int half = lane >> 4;      // 0 = lower (row 2p), 1 = upper (row 2p+1)
    const int q    = lane & 15;      // float4 index within row

    // Zero private accumulators.
    {
        float4* z = &ssum4[0][0][0];
        for (int i = tid; i < NWARPS * N_SYSTEMS * 16; i += 256)
            z[i] = make_float4(0.f, 0.f, 0.f, 0.f);
        if (tid < NWARPS * N_SYSTEMS) (&scount[0][0])[tid] = 0.0f;
    }
    __syncthreads();

    const float4* __restrict__ out4 = (const float4*)out;
    const long long npairs = (long long)(n_rows + 1) >> 1;
    const long long total_warps = (long long)gridDim.x * NWARPS;
    long long p = (long long)blockIdx.x * NWARPS + warp;

    // Prefetch first pair.
    float4 v = make_float4(0.f, 0.f, 0.f, 0.f);
    int my_sys = 0;
    bool valid = false;
    if (p < npairs) {
        long long row = 2 * p + half;
        valid = (row < n_rows);
        if (valid) {
            v = out4[p * 32 + lane];
            my_sys = system[row];
        }
    }

    while (p < npairs) {
        // Prefetch next pair (raises MLP).
        long long pn = p + total_warps;
        float4 vn = make_float4(0.f, 0.f, 0.f, 0.f);
        int sysn = 0;
        bool validn = false;
        if (pn < npairs) {
            long long rown = 2 * pn + half;
            validn = (rown < n_rows);
            if (validn) {
                vn = out4[pn * 32 + lane];
                sysn = system[rown];
            }
        }

        // ---- process current pair ----
        // Sum of squares per row: width-16 butterfly (covers both rows at once).
        float ss = v.x * v.x + v.y * v.y + v.z * v.z + v.w * v.w;
        ss += __shfl_xor_sync(0xFFFFFFFFu, ss, 8);
        ss += __shfl_xor_sync(0xFFFFFFFFu, ss, 4);
        ss += __shfl_xor_sync(0xFFFFFFFFu, ss, 2);
        ss += __shfl_xor_sync(0xFFFFFFFFu, ss, 1);
        float inv = rsqrtf(fmaxf(ss, 1e-24f));   // == 1/max(||x||, 1e-12)

        float4 s;
        s.x = v.x * inv; s.y = v.y * inv; s.z = v.z * inv; s.w = v.w * inv;

        // Detect whether both halves hit the same system (warp-uniform).
        int other_sys = __shfl_xor_sync(0xFFFFFFFFu, my_sys, 16);
        bool other_valid = __shfl_xor_sync(0xFFFFFFFFu, (int)valid, 16);

        if (!(other_valid && valid && other_sys == my_sys)) {
            // Common path: halves write to distinct systems (or one invalid).
            if (valid) {
                float4 a = ssum4[warp][my_sys][q];
                a.x += s.x; a.y += s.y; a.z += s.z; a.w += s.w;
                ssum4[warp][my_sys][q] = a;
                if (q == 0) scount[warp][my_sys] += 1.0f;  // lanes 0 & 16: different addrs
            }
        } else {
            // Rare path (~1/16): same system in both halves; combine to lower half.
            s.x += __shfl_xor_sync(0xFFFFFFFFu, s.x, 16);
            s.y += __shfl_xor_sync(0xFFFFFFFFu, s.y, 16);
            s.z += __shfl_xor_sync(0xFFFFFFFFu, s.z, 16);
            s.w += __shfl_xor_sync(0xFFFFFFFFu, s.w, 16);
            if (half == 0) {
                float4 a = ssum4[warp][my_sys][q];
                a.x += s.x; a.y += s.y; a.z += s.z; a.w += s.w;
                ssum4[warp][my_sys][q] = a;
                if (q == 0) scount[warp][my_sys] += 2.0f;
            }
        }

        v = vn; my_sys = sysn; valid = validn; p = pn;
    }

    __syncthreads();

    // Block flush: reduce the NWARPS private copies, one global atomic per element.
    const float* sf = (const float*)&ssum4[0][0][0];   // [NWARPS][1024]
    for (int i = tid; i < N_SYSTEMS * D; i += 256) {
        float acc = 0.0f;
        #pragma unroll
        for (int w = 0; w < NWARPS; w++) acc += sf[w * (N_SYSTEMS * D) + i];
        if (acc != 0.0f) atomicAdd(&g_sums[i], acc);
    }
    if (tid < N_SYSTEMS) {
        float c = 0.0f;
        #pragma unroll
        for (int w = 0; w < NWARPS; w++) c += scount[w][tid];
        if (c != 0.0f) atomicAdd(&g_counts[tid], c);
    }
}

// Single-block epilogue: means -> Gram -> distance matrix.
__global__ void __launch_bounds__(256) finalize_kernel(float* __restrict__ dist)
{
    __shared__ float means[N_SYSTEMS * D];
    int t = threadIdx.x;

    for (int i = t; i < N_SYSTEMS * D; i += 256) {
        int s = i / D;
        means[i] = g_sums[i] / g_counts[s];
    }
    __syncthreads();

    int i = t >> 4;
    int j = t & 15;
    float dot = 0.0f;
    #pragma unroll
    for (int d = 0; d < D; d++)
        dot += means[i * D + d] * means[j * D + d];

    float v = 0.5f - 0.5f * dot;
    if (i == j) v = 0.0f;
    dist[i * N_SYSTEMS + j] = v;
}

extern "C" void kernel_launch(void* const* d_in, const int* in_sizes, int n_in,
                              void* d_out, int out_size) {
    const float* out_mat = (const float*)d_in[0];
    const int* system = (const int*)d_in[1];
    float* dist = (float*)d_out;
    int n_rows = in_sizes[1];  // system has one entry per row

    zero_scratch_kernel<<<1, 1024>>>();
    accumulate_kernel<<<NBLOCKS, 256>>>(out_mat, system, n_rows);
    finalize_kernel<<<1, 256>>>(dist);
}